// round 12
// baseline (speedup 1.0000x reference)
#include <cuda_runtime.h>
#include <cuda_fp16.h>
#include <cstdint>
#include <math.h>

// ---------------------------------------------------------------------------
// Problem constants — BM=128, warp tile 64x32, 1 CTA/SM
// ---------------------------------------------------------------------------
#define BATCH   4096
#define DIN     128
#define DOUT    128
#define NB      9
#define KPAD    10                 // k per input dim, padded 9 -> 10 (slot 9 = 0)
#define KTOT    (DIN * KPAD)       // 1280
#define KSPLIT  4
#define ISL     (DIN / KSPLIT)     // 32 input dims per split
#define KSLICE  (ISL * KPAD)       // 320 k per split
#define BM      128
#define NTILE   (BATCH / BM)       // 32
#define FCH     8                  // input dims per feat chunk
#define NCH     (ISL / FCH)        // 4 chunks
#define KCH     (FCH * KPAD)       // 80 k rows per chunk (5 k16-steps)

#define ASTR    136                // halves; 272B/row = 68w === 4*odd banks -> CF
#define BSTR    328                // halves; 656B/row -> CF, 16B-aligned

// smem layout (bytes)
#define OFF_BS  0
#define BS_B    (DOUT * BSTR * 2)           // 83968
#define OFF_AS  (OFF_BS + BS_B)
#define AS_STG  (KCH * ASTR * 2)            // 21760 bytes per stage
#define AS_B    (2 * AS_STG)                // 43520 (double-buffered)
#define SMEM_BYTES (OFF_AS + AS_B)          // 127488 -> 1 CTA/SM

// ---------------------------------------------------------------------------
// Device scratch (allocation-free)
// ---------------------------------------------------------------------------
__device__ __half g_Wh[DOUT * KTOT];              // fp16 W*C, [o][k], 320 KB
__device__ float  g_betap[8 * DOUT];              // 8 partial beta slices
__device__ float  g_part[KSPLIT * BATCH * DOUT];  // 8 MB fp32 partials
__device__ int    g_cnt[NTILE];                   // zero-init; reset by reducer

// ---------------------------------------------------------------------------
// Helpers
// ---------------------------------------------------------------------------
__device__ __forceinline__ float tanh_ap(float f) {
    float r; asm("tanh.approx.f32 %0, %1;" : "=f"(r) : "f"(f)); return r;
}
__device__ __forceinline__ float sqrt_ap(float f) {
    float r; asm("sqrt.approx.f32 %0, %1;" : "=f"(r) : "f"(f)); return r;
}
__device__ __forceinline__ uint32_t s2u(const void* p) {
    uint32_t a;
    asm("{ .reg .u64 t; cvta.to.shared.u64 t, %1; cvt.u32.u64 %0, t; }" : "=r"(a) : "l"(p));
    return a;
}
__device__ __forceinline__ void cp16(uint32_t dst, const void* src) {
    asm volatile("cp.async.cg.shared.global [%0], [%1], 16;" :: "r"(dst), "l"(src) : "memory");
}
#define CP_COMMIT() asm volatile("cp.async.commit_group;" ::: "memory")
#define CP_WAIT(n)  asm volatile("cp.async.wait_group %0;" :: "n"(n) : "memory")

__device__ __forceinline__ void ldm_x4(uint32_t* r, uint32_t addr) {
    asm volatile("ldmatrix.sync.aligned.m8n8.x4.shared.b16 {%0,%1,%2,%3}, [%4];"
        : "=r"(r[0]), "=r"(r[1]), "=r"(r[2]), "=r"(r[3]) : "r"(addr));
}
__device__ __forceinline__ void ldm_x4t(uint32_t* r, uint32_t addr) {
    asm volatile("ldmatrix.sync.aligned.m8n8.x4.trans.shared.b16 {%0,%1,%2,%3}, [%4];"
        : "=r"(r[0]), "=r"(r[1]), "=r"(r[2]), "=r"(r[3]) : "r"(addr));
}
__device__ __forceinline__ void mma_f16(float* d, const uint32_t* a, uint32_t b0, uint32_t b1) {
    asm volatile(
        "mma.sync.aligned.m16n8k16.row.col.f32.f16.f16.f32 "
        "{%0,%1,%2,%3}, {%4,%5,%6,%7}, {%8,%9}, {%0,%1,%2,%3};"
        : "+f"(d[0]), "+f"(d[1]), "+f"(d[2]), "+f"(d[3])
        : "r"(a[0]), "r"(a[1]), "r"(a[2]), "r"(a[3]), "r"(b0), "r"(b1));
}

// ---------------------------------------------------------------------------
// Prep: blocks 0..319: g_Wh[o][i*10+2p..2p+1] = fp16(W[i,o,kb]*C[i,o]).
//       blocks 320..327: g_betap[b][o] = sum_{i in [16b,16b+16)} bias*C.
// ---------------------------------------------------------------------------
__global__ void kan_prep(const float* __restrict__ W, const float* __restrict__ C,
                         const float* __restrict__ bias) {
    if (blockIdx.x >= 320) {
        const int b = blockIdx.x - 320;
        const int o = threadIdx.x;
        if (o < DOUT) {
            float s = 0.0f;
            #pragma unroll
            for (int q = 0; q < 16; ++q) {
                int i = b * 16 + q;
                s += bias[i * DOUT + o] * C[i * DOUT + o];
            }
            g_betap[b * DOUT + o] = s;
        }
        return;
    }
    int j = blockIdx.x * blockDim.x + threadIdx.x;   // 0 .. 81919
    int p  = j % 5;
    int io = j / 5;                 // i*128 + o
    int o = io & 127;
    int i = io >> 7;
    float cv = C[io];
    const float* wp = W + (size_t)io * NB + p * 2;
    float v0 = wp[0] * cv;
    float v1 = (p < 4) ? wp[1] * cv : 0.0f;
    ((__half2*)g_Wh)[o * (KTOT / 2) + i * (KPAD / 2) + p] = __floats2half2_rn(v0, v1);
}

// ---------------------------------------------------------------------------
// One basis evaluation -> 10 fp16 k-rows of one A stage
// ---------------------------------------------------------------------------
__device__ __forceinline__ void eval_feat(__half* Ast, int row, int ii, float xv) {
    float ax = fabsf(xv);
    float x2 = xv * xv;
    __half* d = Ast + (ii * KPAD) * ASTR + row;
    d[0 * ASTR] = __float2half_rn(xv);
    d[1 * ASTR] = __float2half_rn(x2);
    d[2 * ASTR] = __float2half_rn(x2 * xv);
    d[3 * ASTR] = __float2half_rn(__expf(xv));
    d[4 * ASTR] = __float2half_rn(__logf(ax + 1.0f));
    d[5 * ASTR] = __float2half_rn(sqrt_ap(ax));
    d[6 * ASTR] = __float2half_rn(tanh_ap(xv));
    d[7 * ASTR] = __float2half_rn(__sinf(xv));
    d[8 * ASTR] = __float2half_rn(ax);
    d[9 * ASTR] = __half(0.0f);
}

// ---------------------------------------------------------------------------
// Main: BM=128 tile, 8 warps (warp tile 64m x 32n), 1 CTA/SM, progressive
// cp.async B, A double-buffered with produce(c+1) overlapping mma(c),
// split-K=4 with fused last-block reduction. Grid (32, 4) = 128 blocks.
// ---------------------------------------------------------------------------
__global__ __launch_bounds__(256, 1)
void kan_main(const float* __restrict__ x, float* __restrict__ out)
{
    extern __shared__ char smem[];
    __half* Bs = (__half*)(smem + OFF_BS);     // [128 n][328], cols 0..319 data
    __half* As = (__half*)(smem + OFF_AS);     // 2 stages of [80 k][136 m]
    __shared__ int s_last;

    const int tid   = threadIdx.x;
    const int lane  = tid & 31;
    const int warp  = tid >> 5;
    const int wm    = warp & 1;          // m warp -> m0 = wm*64
    const int wn    = warp >> 1;         // n warp -> n0 = wn*32
    const int g     = lane >> 2;
    const int tg    = lane & 3;
    const int t4    = lane >> 3;
    const int r8    = lane & 7;
    const int tile  = blockIdx.x;
    const int split = blockIdx.y;
    const int bm0   = tile * BM;
    const int i0    = split * ISL;

    // feat-task coordinates: thread -> row (0..127), 4 dims (fbase..fbase+3)
    const int frow  = tid & 127;
    const int fbase = (tid >> 7) * 4;
    const float* xrow = x + (size_t)(bm0 + frow) * DIN + i0;

    // --- cp.async B slice in 4 progressive groups (20KB each)
    {
        const uint32_t bsb = s2u(Bs);
        const __half*  src0 = g_Wh + (size_t)split * KSLICE;
        #pragma unroll
        for (int c = 0; c < NCH; ++c) {
            #pragma unroll
            for (int jj = 0; jj < 5; ++jj) {
                int j = tid + jj * 256;
                int n = j / 10, q = j - n * 10;
                cp16(bsb + (uint32_t)(n * (BSTR * 2) + c * 160 + q * 16),
                     src0 + (size_t)n * KTOT + c * KCH + q * 8);
            }
            CP_COMMIT();
        }
    }

    // --- prefetch x for chunks 0 and 1
    float xc[4], xn[4];
    #pragma unroll
    for (int q = 0; q < 4; ++q) { xc[q] = xrow[fbase + q]; xn[q] = xrow[FCH + fbase + q]; }

    // --- ldmatrix lane base addresses
    uint32_t aAddr[4], bAddr[2];
    {
        const uint32_t asb = s2u(As), bsb = s2u(Bs);
        #pragma unroll
        for (int mt = 0; mt < 4; ++mt) {
            int m0 = wm * 64 + mt * 16;
            aAddr[mt] = asb + (uint32_t)(((t4 >> 1) * 8 + r8) * ASTR + m0 + (t4 & 1) * 8) * 2;
        }
        #pragma unroll
        for (int p = 0; p < 2; ++p) {
            int n = wn * 32 + p * 16 + (t4 >> 1) * 8 + r8;
            bAddr[p] = bsb + (uint32_t)(n * BSTR + (t4 & 1) * 8) * 2;
        }
    }

    float acc[4][4][4];
    #pragma unroll
    for (int mt = 0; mt < 4; ++mt)
        #pragma unroll
        for (int nt = 0; nt < 4; ++nt)
            #pragma unroll
            for (int e = 0; e < 4; ++e) acc[mt][nt][e] = 0.0f;

    // --- chunk 0 feats into stage 0; wait only for B group 0
    #pragma unroll
    for (int q = 0; q < 4; ++q) eval_feat(As, frow, fbase + q, xc[q]);
    CP_WAIT(3);
    __syncthreads();

    #pragma unroll
    for (int c = 0; c < NCH; ++c) {
        // --- produce chunk c+1 into the other stage (overlaps this mma interval)
        if (c + 1 < NCH) {
            __half* Ast = As + ((c + 1) & 1) * (AS_STG / 2);
            #pragma unroll
            for (int q = 0; q < 4; ++q) eval_feat(Ast, frow, fbase + q, xn[q]);
            if (c + 2 < NCH) {
                #pragma unroll
                for (int q = 0; q < 4; ++q) xn[q] = xrow[(c + 2) * FCH + fbase + q];
            }
        }

        // --- 5 k16-steps on stage c&1
        const uint32_t aStage = (uint32_t)((c & 1) * AS_STG);
        #pragma unroll
        for (int s5 = 0; s5 < 5; ++s5) {
            const uint32_t kaOff = aStage + (uint32_t)(s5 * 16 * ASTR) * 2;
            const uint32_t kbOff = (uint32_t)((c * KCH + s5 * 16)) * 2;
            uint32_t a[4][4], bq[2][4];
            ldm_x4t(a[0], aAddr[0] + kaOff);
            ldm_x4t(a[1], aAddr[1] + kaOff);
            ldm_x4t(a[2], aAddr[2] + kaOff);
            ldm_x4t(a[3], aAddr[3] + kaOff);
            ldm_x4(bq[0], bAddr[0] + kbOff);
            ldm_x4(bq[1], bAddr[1] + kbOff);
            #pragma unroll
            for (int mt = 0; mt < 4; ++mt)
                #pragma unroll
                for (int nt = 0; nt < 4; ++nt)
                    mma_f16(acc[mt][nt], a[mt],
                            bq[nt >> 1][(nt & 1) * 2], bq[nt >> 1][(nt & 1) * 2 + 1]);
        }
        if (c == 0)      CP_WAIT(2);
        else if (c == 1) CP_WAIT(1);
        else if (c == 2) CP_WAIT(0);
        __syncthreads();
    }

    // --- epilogue: write raw partials
    {
        float* base = g_part + (size_t)split * BATCH * DOUT;
        #pragma unroll
        for (int mt = 0; mt < 4; ++mt) {
            int row = bm0 + wm * 64 + mt * 16 + g;
            #pragma unroll
            for (int nt = 0; nt < 4; ++nt) {
                int col = wn * 32 + nt * 8 + tg * 2;
                float* p = base + (size_t)row * DOUT + col;
                *(float2*)p              = make_float2(acc[mt][nt][0], acc[mt][nt][1]);
                *(float2*)(p + 8 * DOUT) = make_float2(acc[mt][nt][2], acc[mt][nt][3]);
            }
        }
    }

    // --- last split block of this tile reduces 4 partial planes + beta -> out
    __threadfence();
    __syncthreads();
    if (tid == 0)
        s_last = (atomicAdd(&g_cnt[tile], 1) == KSPLIT - 1);
    __syncthreads();

    if (s_last) {
        __threadfence();
        // beta = sum of 8 partial slices, staged in smem (Bs area is free now)
        float* sb = (float*)smem;
        if (tid < DOUT) {
            float s = 0.0f;
            #pragma unroll
            for (int b = 0; b < 8; ++b) s += g_betap[b * DOUT + tid];
            sb[tid] = s;
        }
        __syncthreads();

        const float4* pp = (const float4*)g_part;
        const size_t plane = (size_t)BATCH * DOUT / 4;
        const size_t base4 = (size_t)bm0 * (DOUT / 4);
        #pragma unroll
        for (int idx = tid; idx < BM * DOUT / 4; idx += 256) {
            size_t o = base4 + idx;
            float4 p0 = __ldcg(pp + o);
            float4 p1 = __ldcg(pp + plane + o);
            float4 p2 = __ldcg(pp + 2 * plane + o);
            float4 p3 = __ldcg(pp + 3 * plane + o);
            float4 be = ((const float4*)sb)[idx & 31];
            float4 s;
            s.x = (p0.x + p1.x) + (p2.x + p3.x) + be.x;
            s.y = (p0.y + p1.y) + (p2.y + p3.y) + be.y;
            s.z = (p0.z + p1.z) + (p2.z + p3.z) + be.z;
            s.w = (p0.w + p1.w) + (p2.w + p3.w) + be.w;
            ((float4*)out)[o] = s;
        }
        __syncthreads();
        if (tid == 0) g_cnt[tile] = 0;
    }
}

// ---------------------------------------------------------------------------
extern "C" void kernel_launch(void* const* d_in, const int* in_sizes, int n_in,
                              void* d_out, int out_size) {
    const float* x    = (const float*)d_in[0];   // [4096,128]
    const float* W    = (const float*)d_in[1];   // [128,128,9]
    const float* bias = (const float*)d_in[2];   // [128,128]
    const float* C    = (const float*)d_in[3];   // [128,128]
    float* out        = (float*)d_out;           // [4096,128]
    (void)in_sizes; (void)n_in; (void)out_size;

    cudaFuncSetAttribute(kan_main, cudaFuncAttributeMaxDynamicSharedMemorySize, SMEM_BYTES);

    kan_prep<<<328, 256>>>(W, C, bias);
    kan_main<<<dim3(NTILE, KSPLIT), 256, SMEM_BYTES>>>(x, out);
}

// round 13
// speedup vs baseline: 1.0949x; 1.0949x over previous
#include <cuda_runtime.h>
#include <cuda_fp16.h>
#include <cstdint>
#include <math.h>

// ---------------------------------------------------------------------------
// Problem constants (R11 geometry — best measured main — + fused in-kernel prep)
// ---------------------------------------------------------------------------
#define BATCH   4096
#define DIN     128
#define DOUT    128
#define NB      9
#define KPAD    10                 // k per input dim, padded 9 -> 10 (slot 9 = 0)
#define KTOT    (DIN * KPAD)       // 1280
#define KSPLIT  4
#define ISL     (DIN / KSPLIT)     // 32 input dims per split
#define KSLICE  (ISL * KPAD)       // 320 k per split
#define BM      64
#define NTILE   (BATCH / BM)       // 64
#define GRIDN   (NTILE * KSPLIT)   // 256 blocks — all co-resident at 2 CTAs/SM
#define FCH     8                  // input dims per feat chunk
#define NCH     (ISL / FCH)        // 4 chunks
#define KCH     (FCH * KPAD)       // 80 k rows per chunk (5 k16-steps)

#define ASTR    72                 // halves; 144B/row -> ldmatrix CF
#define BSTR    328                // halves; 656B/row -> CF, 16B-aligned

// smem layout (bytes)
#define OFF_BS  0
#define BS_B    (DOUT * BSTR * 2)           // 83968
#define OFF_AS  (OFF_BS + BS_B)
#define AS_STG  (KCH * ASTR * 2)            // 11520 bytes per stage
#define AS_B    (2 * AS_STG)                // 23040 (double-buffered)
#define SMEM_BYTES (OFF_AS + AS_B)          // 107008 -> 2 CTAs/SM (all 256 resident)

// ---------------------------------------------------------------------------
// Device scratch (allocation-free)
// ---------------------------------------------------------------------------
__device__ __half g_Wh[DOUT * KTOT];              // fp16 W*C, [o][k], 320 KB
__device__ float  g_betap[8 * DOUT];              // 8 partial beta slices
__device__ float  g_part[KSPLIT * BATCH * DOUT];  // 8 MB fp32 partials
__device__ int    g_cnt[NTILE];                   // zero-init; reset by reducer
__device__ int    g_s1, g_s2;                     // grid-sync counters (self-reset)

// ---------------------------------------------------------------------------
// Helpers
// ---------------------------------------------------------------------------
__device__ __forceinline__ float tanh_ap(float f) {
    float r; asm("tanh.approx.f32 %0, %1;" : "=f"(r) : "f"(f)); return r;
}
__device__ __forceinline__ float sqrt_ap(float f) {
    float r; asm("sqrt.approx.f32 %0, %1;" : "=f"(r) : "f"(f)); return r;
}
__device__ __forceinline__ uint32_t s2u(const void* p) {
    uint32_t a;
    asm("{ .reg .u64 t; cvta.to.shared.u64 t, %1; cvt.u32.u64 %0, t; }" : "=r"(a) : "l"(p));
    return a;
}
__device__ __forceinline__ void cp16(uint32_t dst, const void* src) {
    asm volatile("cp.async.cg.shared.global [%0], [%1], 16;" :: "r"(dst), "l"(src) : "memory");
}
#define CP_COMMIT() asm volatile("cp.async.commit_group;" ::: "memory")
#define CP_WAIT(n)  asm volatile("cp.async.wait_group %0;" :: "n"(n) : "memory")

__device__ __forceinline__ void ldm_x4(uint32_t* r, uint32_t addr) {
    asm volatile("ldmatrix.sync.aligned.m8n8.x4.shared.b16 {%0,%1,%2,%3}, [%4];"
        : "=r"(r[0]), "=r"(r[1]), "=r"(r[2]), "=r"(r[3]) : "r"(addr));
}
__device__ __forceinline__ void ldm_x4t(uint32_t* r, uint32_t addr) {
    asm volatile("ldmatrix.sync.aligned.m8n8.x4.trans.shared.b16 {%0,%1,%2,%3}, [%4];"
        : "=r"(r[0]), "=r"(r[1]), "=r"(r[2]), "=r"(r[3]) : "r"(addr));
}
__device__ __forceinline__ void mma_f16(float* d, const uint32_t* a, uint32_t b0, uint32_t b1) {
    asm volatile(
        "mma.sync.aligned.m16n8k16.row.col.f32.f16.f16.f32 "
        "{%0,%1,%2,%3}, {%4,%5,%6,%7}, {%8,%9}, {%0,%1,%2,%3};"
        : "+f"(d[0]), "+f"(d[1]), "+f"(d[2]), "+f"(d[3])
        : "r"(a[0]), "r"(a[1]), "r"(a[2]), "r"(a[3]), "r"(b0), "r"(b1));
}

// ---------------------------------------------------------------------------
// One basis evaluation -> 10 fp16 k-rows of one A stage (CF contiguous stores)
// ---------------------------------------------------------------------------
__device__ __forceinline__ void eval_feat(__half* Ast, int row, int ii, float xv) {
    float ax = fabsf(xv);
    float x2 = xv * xv;
    __half* d = Ast + (ii * KPAD) * ASTR + row;
    d[0 * ASTR] = __float2half_rn(xv);
    d[1 * ASTR] = __float2half_rn(x2);
    d[2 * ASTR] = __float2half_rn(x2 * xv);
    d[3 * ASTR] = __float2half_rn(__expf(xv));
    d[4 * ASTR] = __float2half_rn(__logf(ax + 1.0f));
    d[5 * ASTR] = __float2half_rn(sqrt_ap(ax));
    d[6 * ASTR] = __float2half_rn(tanh_ap(xv));
    d[7 * ASTR] = __float2half_rn(__sinf(xv));
    d[8 * ASTR] = __float2half_rn(ax);
    d[9 * ASTR] = __half(0.0f);
}

// ---------------------------------------------------------------------------
// SINGLE fused kernel:
//   Phase 0: distributed W*C -> fp16 conversion (320 half2 per block, coalesced)
//            + 8 beta partial blocks; software grid barrier (all blocks resident).
//   Phase 1: R11 main — progressive cp.async B, double-buffered A with
//            produce/mma overlap, fp16 ldmatrix mma, split-K=4, fused reduce.
// Grid (64, 4) = 256 blocks, 256 threads, 2 CTAs/SM.
// ---------------------------------------------------------------------------
__global__ __launch_bounds__(256, 2)
void kan_main(const float* __restrict__ x, const float* __restrict__ W,
              const float* __restrict__ bias, const float* __restrict__ C,
              float* __restrict__ out)
{
    extern __shared__ char smem[];
    __half* Bs = (__half*)(smem + OFF_BS);     // [128 n][328], cols 0..319 data
    __half* As = (__half*)(smem + OFF_AS);     // 2 stages of [80 k][72 m]
    __shared__ int s_last;

    const int tid   = threadIdx.x;
    const int lane  = tid & 31;
    const int warp  = tid >> 5;
    const int wm    = warp & 1;
    const int wn    = warp >> 1;
    const int g     = lane >> 2;
    const int tg    = lane & 3;
    const int t4    = lane >> 3;
    const int r8    = lane & 7;
    const int tile  = blockIdx.x;
    const int split = blockIdx.y;
    const int bm0   = tile * BM;
    const int i0    = split * ISL;
    const int bid   = blockIdx.y * NTILE + blockIdx.x;   // 0..255

    // ======================= Phase 0: fused prep =======================
    {
        // this block's 320 contiguous half2 of g_Wh (1.25 KB coalesced)
        #pragma unroll
        for (int jj = 0; jj < 2; ++jj) {
            int t = tid + jj * 256;
            if (jj == 0 || t < 320) {
                int j  = bid * 320 + t;          // half2 index
                int o  = j / 640;
                int r  = j - o * 640;
                int i  = r / 5;
                int p  = r - i * 5;
                int io = i * DOUT + o;
                float cv = C[io];
                const float* wp = W + (size_t)io * NB + p * 2;
                float v0 = wp[0] * cv;
                float v1 = (p < 4) ? wp[1] * cv : 0.0f;
                ((__half2*)g_Wh)[j] = __floats2half2_rn(v0, v1);
            }
        }
        // beta partials on blocks 0..7
        if (bid < 8 && tid < DOUT) {
            float s = 0.0f;
            #pragma unroll
            for (int q = 0; q < 16; ++q) {
                int i = bid * 16 + q;
                s += bias[i * DOUT + tid] * C[i * DOUT + tid];
            }
            g_betap[bid * DOUT + tid] = s;
        }
        // software grid barrier (all 256 blocks co-resident; self-resetting)
        __syncthreads();
        if (tid == 0) {
            __threadfence();
            atomicAdd(&g_s1, 1);
            while (atomicAdd(&g_s1, 0) < GRIDN) __nanosleep(64);
            __threadfence();
            int v = atomicAdd(&g_s2, 1);
            if (v == GRIDN - 1) { atomicExch(&g_s1, 0); atomicExch(&g_s2, 0); }
        }
        __syncthreads();
    }

    // ======================= Phase 1: main GEMM =======================
    const int frow = tid & 63;
    const int fii0 = tid >> 6;           // task 0: ii = fii0, task 1: ii = fii0+4
    const float* xrow = x + (size_t)(bm0 + frow) * DIN + i0;

    // --- cp.async B slice in 4 progressive groups (20KB each)
    {
        const uint32_t bsb = s2u(Bs);
        const __half*  src0 = g_Wh + (size_t)split * KSLICE;
        #pragma unroll
        for (int c = 0; c < NCH; ++c) {
            #pragma unroll
            for (int jj = 0; jj < 5; ++jj) {
                int j = tid + jj * 256;
                int n = j / 10, q = j - n * 10;
                cp16(bsb + (uint32_t)(n * (BSTR * 2) + c * 160 + q * 16),
                     src0 + (size_t)n * KTOT + c * KCH + q * 8);
            }
            CP_COMMIT();
        }
    }

    // --- prefetch x for chunks 0 and 1
    float xc0a = xrow[fii0],          xc0b = xrow[fii0 + 4];
    float xna  = xrow[FCH + fii0],    xnb  = xrow[FCH + fii0 + 4];

    // --- ldmatrix lane base addresses
    uint32_t aAddr[2], bAddr[2];
    {
        const uint32_t asb = s2u(As), bsb = s2u(Bs);
        #pragma unroll
        for (int mt = 0; mt < 2; ++mt) {
            int m0 = wm * 32 + mt * 16;
            aAddr[mt] = asb + (uint32_t)(((t4 >> 1) * 8 + r8) * ASTR + m0 + (t4 & 1) * 8) * 2;
        }
        #pragma unroll
        for (int p = 0; p < 2; ++p) {
            int n = wn * 32 + p * 16 + (t4 >> 1) * 8 + r8;
            bAddr[p] = bsb + (uint32_t)(n * BSTR + (t4 & 1) * 8) * 2;
        }
    }

    float acc[2][4][4];
    #pragma unroll
    for (int mt = 0; mt < 2; ++mt)
        #pragma unroll
        for (int nt = 0; nt < 4; ++nt)
            #pragma unroll
            for (int e = 0; e < 4; ++e) acc[mt][nt][e] = 0.0f;

    // --- chunk 0 feats into stage 0; wait only for B group 0
    eval_feat(As, frow, fii0,     xc0a);
    eval_feat(As, frow, fii0 + 4, xc0b);
    CP_WAIT(3);
    __syncthreads();

    #pragma unroll
    for (int c = 0; c < NCH; ++c) {
        // --- produce chunk c+1 into the other stage (overlaps this mma interval)
        if (c + 1 < NCH) {
            __half* Ast = As + ((c + 1) & 1) * (AS_STG / 2);
            eval_feat(Ast, frow, fii0,     xna);
            eval_feat(Ast, frow, fii0 + 4, xnb);
            if (c + 2 < NCH) {
                xna = xrow[(c + 2) * FCH + fii0];
                xnb = xrow[(c + 2) * FCH + fii0 + 4];
            }
        }

        // --- 5 k16-steps on stage c&1
        const uint32_t aStage = (uint32_t)((c & 1) * AS_STG);
        #pragma unroll
        for (int s5 = 0; s5 < 5; ++s5) {
            const uint32_t kaOff = aStage + (uint32_t)(s5 * 16 * ASTR) * 2;
            const uint32_t kbOff = (uint32_t)((c * KCH + s5 * 16)) * 2;
            uint32_t a[2][4], bq[2][4];
            ldm_x4t(a[0], aAddr[0] + kaOff);
            ldm_x4t(a[1], aAddr[1] + kaOff);
            ldm_x4(bq[0], bAddr[0] + kbOff);
            ldm_x4(bq[1], bAddr[1] + kbOff);
            #pragma unroll
            for (int mt = 0; mt < 2; ++mt)
                #pragma unroll
                for (int nt = 0; nt < 4; ++nt)
                    mma_f16(acc[mt][nt], a[mt],
                            bq[nt >> 1][(nt & 1) * 2], bq[nt >> 1][(nt & 1) * 2 + 1]);
        }
        if (c == 0)      CP_WAIT(2);
        else if (c == 1) CP_WAIT(1);
        else if (c == 2) CP_WAIT(0);
        __syncthreads();
    }

    // --- epilogue: write raw partials
    {
        float* base = g_part + (size_t)split * BATCH * DOUT;
        #pragma unroll
        for (int nt = 0; nt < 4; ++nt) {
            int col = wn * 32 + nt * 8 + tg * 2;
            #pragma unroll
            for (int mt = 0; mt < 2; ++mt) {
                int row = bm0 + wm * 32 + mt * 16 + g;
                float* p = base + (size_t)row * DOUT + col;
                *(float2*)p              = make_float2(acc[mt][nt][0], acc[mt][nt][1]);
                *(float2*)(p + 8 * DOUT) = make_float2(acc[mt][nt][2], acc[mt][nt][3]);
            }
        }
    }

    // --- last split block of this tile reduces 4 partial planes + beta -> out
    __threadfence();
    __syncthreads();
    if (tid == 0)
        s_last = (atomicAdd(&g_cnt[tile], 1) == KSPLIT - 1);
    __syncthreads();

    if (s_last) {
        __threadfence();
        // beta = sum of 8 partial slices, staged in freed smem
        float* sb = (float*)smem;
        if (tid < DOUT) {
            float s = 0.0f;
            #pragma unroll
            for (int b = 0; b < 8; ++b) s += __ldcg(g_betap + b * DOUT + tid);
            sb[tid] = s;
        }
        __syncthreads();

        const float4* pp = (const float4*)g_part;
        const size_t plane = (size_t)BATCH * DOUT / 4;
        const size_t base4 = (size_t)bm0 * (DOUT / 4);
        #pragma unroll
        for (int idx = tid; idx < BM * DOUT / 4; idx += 256) {
            size_t o = base4 + idx;
            float4 p0 = __ldcg(pp + o);
            float4 p1 = __ldcg(pp + plane + o);
            float4 p2 = __ldcg(pp + 2 * plane + o);
            float4 p3 = __ldcg(pp + 3 * plane + o);
            float4 be = ((const float4*)sb)[idx & 31];
            float4 s;
            s.x = (p0.x + p1.x) + (p2.x + p3.x) + be.x;
            s.y = (p0.y + p1.y) + (p2.y + p3.y) + be.y;
            s.z = (p0.z + p1.z) + (p2.z + p3.z) + be.z;
            s.w = (p0.w + p1.w) + (p2.w + p3.w) + be.w;
            ((float4*)out)[o] = s;
        }
        __syncthreads();
        if (tid == 0) g_cnt[tile] = 0;
    }
}

// ---------------------------------------------------------------------------
extern "C" void kernel_launch(void* const* d_in, const int* in_sizes, int n_in,
                              void* d_out, int out_size) {
    const float* x    = (const float*)d_in[0];   // [4096,128]
    const float* W    = (const float*)d_in[1];   // [128,128,9]
    const float* bias = (const float*)d_in[2];   // [128,128]
    const float* C    = (const float*)d_in[3];   // [128,128]
    float* out        = (float*)d_out;           // [4096,128]
    (void)in_sizes; (void)n_in; (void)out_size;

    cudaFuncSetAttribute(kan_main, cudaFuncAttributeMaxDynamicSharedMemorySize, SMEM_BYTES);
    kan_main<<<dim3(NTILE, KSPLIT), 256, SMEM_BYTES>>>(x, W, bias, C, out);
}

// round 15
// speedup vs baseline: 1.1099x; 1.0137x over previous
#include <cuda_runtime.h>
#include <cuda_fp16.h>
#include <cstdint>
#include <math.h>

// ---------------------------------------------------------------------------
// Problem constants — KPAD=9 (zero padding), fused prep + cheap grid barrier
// ---------------------------------------------------------------------------
#define BATCH   4096
#define DIN     128
#define DOUT    128
#define NB      9
#define KTOT    (DIN * NB)         // 1152, k = i*9 + kb  (NO padding)
#define KSPLIT  4
#define ISL     (DIN / KSPLIT)     // 32 input dims per split
#define KSLICE  (ISL * NB)         // 288 k per split
#define BM      64
#define NTILE   (BATCH / BM)       // 64
#define GRIDN   (NTILE * KSPLIT)   // 256 blocks, all co-resident at 2 CTAs/SM
#define FCH     16                 // input dims per chunk (144 k = 9 k16-steps)
#define NCH     2
#define KCH     (FCH * NB)         // 144

#define ASTR    72                 // halves; 144B/row = 36w === 4*odd -> ldmatrix CF
#define BSTR    296                // halves; 592B/row = 148w === 4*odd -> CF, 16B-aligned

// smem layout (bytes)
#define OFF_BS  0
#define BS_B    (DOUT * BSTR * 2)           // 75776
#define OFF_AS  (OFF_BS + BS_B)
#define AS_B    (KCH * ASTR * 2)            // 20736 (single buffer)
#define SMEM_BYTES (OFF_AS + AS_B)          // 96512 -> 2 CTAs/SM

// ---------------------------------------------------------------------------
// Device scratch (allocation-free)
// ---------------------------------------------------------------------------
__device__ __half g_Wh[DOUT * KTOT];              // fp16 W*C, [o][k], 288 KB
__device__ float  g_betap[32 * DOUT];             // 32 partial beta slices
__device__ float  g_part[KSPLIT * BATCH * DOUT];  // 8 MB fp32 partials
__device__ int    g_cnt[NTILE];                   // zero-init; reset by reducer
__device__ int    g_s1, g_s2;                     // grid-sync counters (self-reset)

// ---------------------------------------------------------------------------
// Helpers
// ---------------------------------------------------------------------------
__device__ __forceinline__ float tanh_ap(float f) {
    float r; asm("tanh.approx.f32 %0, %1;" : "=f"(r) : "f"(f)); return r;
}
__device__ __forceinline__ float sqrt_ap(float f) {
    float r; asm("sqrt.approx.f32 %0, %1;" : "=f"(r) : "f"(f)); return r;
}
__device__ __forceinline__ uint32_t s2u(const void* p) {
    uint32_t a;
    asm("{ .reg .u64 t; cvta.to.shared.u64 t, %1; cvt.u32.u64 %0, t; }" : "=r"(a) : "l"(p));
    return a;
}
__device__ __forceinline__ void cp16(uint32_t dst, const void* src) {
    asm volatile("cp.async.cg.shared.global [%0], [%1], 16;" :: "r"(dst), "l"(src) : "memory");
}
#define CP_COMMIT() asm volatile("cp.async.commit_group;" ::: "memory")
#define CP_WAIT(n)  asm volatile("cp.async.wait_group %0;" :: "n"(n) : "memory")

__device__ __forceinline__ void ldm_x4(uint32_t* r, uint32_t addr) {
    asm volatile("ldmatrix.sync.aligned.m8n8.x4.shared.b16 {%0,%1,%2,%3}, [%4];"
        : "=r"(r[0]), "=r"(r[1]), "=r"(r[2]), "=r"(r[3]) : "r"(addr));
}
__device__ __forceinline__ void ldm_x4t(uint32_t* r, uint32_t addr) {
    asm volatile("ldmatrix.sync.aligned.m8n8.x4.trans.shared.b16 {%0,%1,%2,%3}, [%4];"
        : "=r"(r[0]), "=r"(r[1]), "=r"(r[2]), "=r"(r[3]) : "r"(addr));
}
__device__ __forceinline__ void mma_f16(float* d, const uint32_t* a, uint32_t b0, uint32_t b1) {
    asm volatile(
        "mma.sync.aligned.m16n8k16.row.col.f32.f16.f16.f32 "
        "{%0,%1,%2,%3}, {%4,%5,%6,%7}, {%8,%9}, {%0,%1,%2,%3};"
        : "+f"(d[0]), "+f"(d[1]), "+f"(d[2]), "+f"(d[3])
        : "r"(a[0]), "r"(a[1]), "r"(a[2]), "r"(a[3]), "r"(b0), "r"(b1));
}

// ---------------------------------------------------------------------------
// One basis evaluation -> 9 fp16 k-rows of the A buffer (CF contiguous stores)
// ---------------------------------------------------------------------------
__device__ __forceinline__ void eval_feat(__half* Ast, int row, int ii, float xv) {
    float ax = fabsf(xv);
    float x2 = xv * xv;
    __half* d = Ast + (ii * NB) * ASTR + row;
    d[0 * ASTR] = __float2half_rn(xv);
    d[1 * ASTR] = __float2half_rn(x2);
    d[2 * ASTR] = __float2half_rn(x2 * xv);
    d[3 * ASTR] = __float2half_rn(__expf(xv));
    d[4 * ASTR] = __float2half_rn(__logf(ax + 1.0f));
    d[5 * ASTR] = __float2half_rn(sqrt_ap(ax));
    d[6 * ASTR] = __float2half_rn(tanh_ap(xv));
    d[7 * ASTR] = __float2half_rn(__sinf(xv));
    d[8 * ASTR] = __float2half_rn(ax);
}

// ---------------------------------------------------------------------------
// SINGLE fused kernel. Phase 0: distributed W*C->fp16 (288 half2/block) +
// 32 beta-partial blocks + volatile-LD grid barrier. Phase 1: fp16 ldmatrix
// mma with K=1152 (no padding), progressive cp.async B, split-K=4, fused
// last-block reduction. Grid (64, 4) = 256 blocks, 256 threads, 2 CTAs/SM.
// ---------------------------------------------------------------------------
__global__ __launch_bounds__(256, 2)
void kan_main(const float* __restrict__ x, const float* __restrict__ W,
              const float* __restrict__ bias, const float* __restrict__ C,
              float* __restrict__ out)
{
    extern __shared__ char smem[];
    __half* Bs = (__half*)(smem + OFF_BS);     // [128 n][296], cols 0..287 data
    __half* As = (__half*)(smem + OFF_AS);     // [144 k][72 m]
    __shared__ int s_last;

    const int tid   = threadIdx.x;
    const int lane  = tid & 31;
    const int warp  = tid >> 5;
    const int wm    = warp & 1;
    const int wn    = warp >> 1;
    const int g     = lane >> 2;
    const int tg    = lane & 3;
    const int t4    = lane >> 3;
    const int r8    = lane & 7;
    const int tile  = blockIdx.x;
    const int split = blockIdx.y;
    const int bm0   = tile * BM;
    const int i0    = split * ISL;
    const int bid   = blockIdx.y * NTILE + blockIdx.x;   // 0..255

    // ======================= Phase 0: fused prep =======================
    {
        // this block's 288 contiguous half2 of g_Wh (1.125 KB coalesced store)
        #pragma unroll
        for (int jj = 0; jj < 2; ++jj) {
            int t = tid + jj * 256;
            if (t < 288) {                       // FIXED guard (R14 bug: t<32)
                int j = bid * 288 + t;           // half2 index into g_Wh
                int o = j / (KTOT / 2);
                int r = j - o * (KTOT / 2);
                int k0 = 2 * r;
                int i1 = k0 / NB,       kb1 = k0 - i1 * NB;
                int i2 = (k0 + 1) / NB, kb2 = (k0 + 1) - i2 * NB;
                float v0 = W[((size_t)i1 * DOUT + o) * NB + kb1] * C[i1 * DOUT + o];
                float v1 = W[((size_t)i2 * DOUT + o) * NB + kb2] * C[i2 * DOUT + o];
                ((__half2*)g_Wh)[j] = __floats2half2_rn(v0, v1);
            }
        }
        // beta partials on blocks 0..31 (4 input dims each)
        if (bid < 32 && tid < DOUT) {
            float s = 0.0f;
            #pragma unroll
            for (int q = 0; q < 4; ++q) {
                int i = bid * 4 + q;
                s += bias[i * DOUT + tid] * C[i * DOUT + tid];
            }
            g_betap[bid * DOUT + tid] = s;
        }
        // grid barrier: RMW arrive, volatile-LD poll (no atomic-RMW spin)
        __syncthreads();
        if (tid == 0) {
            __threadfence();
            atomicAdd(&g_s1, 1);
            while (*(volatile int*)&g_s1 < GRIDN) __nanosleep(32);
            __threadfence();
            int v = atomicAdd(&g_s2, 1);
            if (v == GRIDN - 1) { atomicExch(&g_s1, 0); atomicExch(&g_s2, 0); }
        }
        __syncthreads();
    }

    // ======================= Phase 1: main GEMM =======================
    const int frow  = tid & 63;
    const int fbase = (tid >> 6) * 4;    // 4 dims per thread per chunk
    const float* xrow = x + (size_t)(bm0 + frow) * DIN + i0;

    // --- cp.async B slice [128 n][288 k] in 2 progressive groups (one per chunk)
    {
        const uint32_t bsb = s2u(Bs);
        const __half*  src0 = g_Wh + (size_t)split * KSLICE;
        #pragma unroll
        for (int c = 0; c < NCH; ++c) {
            #pragma unroll
            for (int jj = 0; jj < 9; ++jj) {
                int j = tid + jj * 256;          // 2304 x 16B per group
                int n = j / 18, q = j - n * 18;
                cp16(bsb + (uint32_t)(n * (BSTR * 2) + c * (KCH * 2) + q * 16),
                     src0 + (size_t)n * KTOT + c * KCH + q * 8);
            }
            CP_COMMIT();
        }
    }

    // --- prefetch x for both chunks
    float xc[4], xn[4];
    #pragma unroll
    for (int q = 0; q < 4; ++q) {
        xc[q] = xrow[fbase + q];
        xn[q] = xrow[FCH + fbase + q];
    }

    // --- ldmatrix lane base addresses
    uint32_t aAddr[2], bAddr[2];
    {
        const uint32_t asb = s2u(As), bsb = s2u(Bs);
        #pragma unroll
        for (int mt = 0; mt < 2; ++mt) {
            int m0 = wm * 32 + mt * 16;
            aAddr[mt] = asb + (uint32_t)(((t4 >> 1) * 8 + r8) * ASTR + m0 + (t4 & 1) * 8) * 2;
        }
        #pragma unroll
        for (int p = 0; p < 2; ++p) {
            int n = wn * 32 + p * 16 + (t4 >> 1) * 8 + r8;
            bAddr[p] = bsb + (uint32_t)(n * BSTR + (t4 & 1) * 8) * 2;
        }
    }

    float acc[2][4][4];
    #pragma unroll
    for (int mt = 0; mt < 2; ++mt)
        #pragma unroll
        for (int nt = 0; nt < 4; ++nt)
            #pragma unroll
            for (int e = 0; e < 4; ++e) acc[mt][nt][e] = 0.0f;

    // --- chunk 0 feats; wait for B group 0
    #pragma unroll
    for (int q = 0; q < 4; ++q) eval_feat(As, frow, fbase + q, xc[q]);
    CP_WAIT(1);
    __syncthreads();

    #pragma unroll
    for (int c = 0; c < NCH; ++c) {
        // --- 9 k16-steps on the A buffer
        #pragma unroll
        for (int s9 = 0; s9 < 9; ++s9) {
            const uint32_t kaOff = (uint32_t)(s9 * 16 * ASTR) * 2;
            const uint32_t kbOff = (uint32_t)((c * KCH + s9 * 16)) * 2;
            uint32_t a[2][4], bq[2][4];
            ldm_x4t(a[0], aAddr[0] + kaOff);
            ldm_x4t(a[1], aAddr[1] + kaOff);
            ldm_x4(bq[0], bAddr[0] + kbOff);
            ldm_x4(bq[1], bAddr[1] + kbOff);
            #pragma unroll
            for (int mt = 0; mt < 2; ++mt)
                #pragma unroll
                for (int nt = 0; nt < 4; ++nt)
                    mma_f16(acc[mt][nt], a[mt],
                            bq[nt >> 1][(nt & 1) * 2], bq[nt >> 1][(nt & 1) * 2 + 1]);
        }
        if (c == 0) {
            __syncthreads();     // A reads done
            #pragma unroll
            for (int q = 0; q < 4; ++q) eval_feat(As, frow, fbase + q, xn[q]);
            CP_WAIT(0);
            __syncthreads();     // chunk-1 feats + B group 1 visible
        }
    }

    // --- epilogue: write raw partials
    {
        float* base = g_part + (size_t)split * BATCH * DOUT;
        #pragma unroll
        for (int nt = 0; nt < 4; ++nt) {
            int col = wn * 32 + nt * 8 + tg * 2;
            #pragma unroll
            for (int mt = 0; mt < 2; ++mt) {
                int row = bm0 + wm * 32 + mt * 16 + g;
                float* p = base + (size_t)row * DOUT + col;
                *(float2*)p              = make_float2(acc[mt][nt][0], acc[mt][nt][1]);
                *(float2*)(p + 8 * DOUT) = make_float2(acc[mt][nt][2], acc[mt][nt][3]);
            }
        }
    }

    // --- last split block of this tile reduces 4 partial planes + beta -> out
    __threadfence();
    __syncthreads();
    if (tid == 0)
        s_last = (atomicAdd(&g_cnt[tile], 1) == KSPLIT - 1);
    __syncthreads();

    if (s_last) {
        __threadfence();
        float* sb = (float*)smem;     // Bs area is free now
        if (tid < DOUT) {
            float s = 0.0f;
            #pragma unroll
            for (int b = 0; b < 32; ++b) s += __ldcg(g_betap + b * DOUT + tid);
            sb[tid] = s;
        }
        __syncthreads();

        const float4* pp = (const float4*)g_part;
        const size_t plane = (size_t)BATCH * DOUT / 4;
        const size_t base4 = (size_t)bm0 * (DOUT / 4);
        #pragma unroll
        for (int idx = tid; idx < BM * DOUT / 4; idx += 256) {
            size_t o = base4 + idx;
            float4 p0 = __ldcg(pp + o);
            float4 p1 = __ldcg(pp + plane + o);
            float4 p2 = __ldcg(pp + 2 * plane + o);
            float4 p3 = __ldcg(pp + 3 * plane + o);
            float4 be = ((const float4*)sb)[idx & 31];
            float4 s;
            s.x = (p0.x + p1.x) + (p2.x + p3.x) + be.x;
            s.y = (p0.y + p1.y) + (p2.y + p3.y) + be.y;
            s.z = (p0.z + p1.z) + (p2.z + p3.z) + be.z;
            s.w = (p0.w + p1.w) + (p2.w + p3.w) + be.w;
            ((float4*)out)[o] = s;
        }
        __syncthreads();
        if (tid == 0) g_cnt[tile] = 0;
    }
}

// ---------------------------------------------------------------------------
extern "C" void kernel_launch(void* const* d_in, const int* in_sizes, int n_in,
                              void* d_out, int out_size) {
    const float* x    = (const float*)d_in[0];   // [4096,128]
    const float* W    = (const float*)d_in[1];   // [128,128,9]
    const float* bias = (const float*)d_in[2];   // [128,128]
    const float* C    = (const float*)d_in[3];   // [128,128]
    float* out        = (float*)d_out;           // [4096,128]
    (void)in_sizes; (void)n_in; (void)out_size;

    cudaFuncSetAttribute(kan_main, cudaFuncAttributeMaxDynamicSharedMemorySize, SMEM_BYTES);
    kan_main<<<dim3(NTILE, KSPLIT), 256, SMEM_BYTES>>>(x, W, bias, C, out);
}

// round 17
// speedup vs baseline: 1.1395x; 1.0266x over previous
#include <cuda_runtime.h>
#include <cuda_fp16.h>
#include <cstdint>
#include <math.h>

// ---------------------------------------------------------------------------
// Problem constants — K=1152 (no padding), two launches, flat parallel prep
// ---------------------------------------------------------------------------
#define BATCH   4096
#define DIN     128
#define DOUT    128
#define NB      9
#define KTOT    (DIN * NB)         // 1152, k = i*9 + kb
#define KSPLIT  4
#define ISL     (DIN / KSPLIT)     // 32 input dims per split
#define KSLICE  (ISL * NB)         // 288 k per split
#define BM      64
#define NTILE   (BATCH / BM)       // 64
#define FCH     16                 // input dims per chunk (144 k = 9 k16-steps)
#define NCH     2
#define KCH     (FCH * NB)         // 144

// prep grid: 256 conversion blocks (256*288 = 73728 half2 = |g_Wh|/2 exactly)
#define CONV_BLKS 256
#define BETA_BLKS 32
#define PREP_BLKS (CONV_BLKS + BETA_BLKS)   // 288

#define ASTR    72                 // halves; 144B/row -> ldmatrix CF
#define BSTR    296                // halves; 592B/row -> CF, 16B-aligned

// smem layout (bytes)
#define OFF_BS  0
#define BS_B    (DOUT * BSTR * 2)           // 75776
#define OFF_AS  (OFF_BS + BS_B)
#define AS_B    (KCH * ASTR * 2)            // 20736 (single buffer)
#define SMEM_BYTES (OFF_AS + AS_B)          // 96512 -> 2 CTAs/SM

// ---------------------------------------------------------------------------
// Device scratch (allocation-free)
// ---------------------------------------------------------------------------
__device__ __half g_Wh[DOUT * KTOT];              // fp16 W*C, [o][k], 288 KB
__device__ float  g_betap[BETA_BLKS * DOUT];      // 32 partial beta slices
__device__ float  g_part[KSPLIT * BATCH * DOUT];  // 8 MB fp32 partials
__device__ int    g_cnt[NTILE];                   // zero-init; reset by reducer

// ---------------------------------------------------------------------------
// Helpers
// ---------------------------------------------------------------------------
__device__ __forceinline__ float tanh_ap(float f) {
    float r; asm("tanh.approx.f32 %0, %1;" : "=f"(r) : "f"(f)); return r;
}
__device__ __forceinline__ float sqrt_ap(float f) {
    float r; asm("sqrt.approx.f32 %0, %1;" : "=f"(r) : "f"(f)); return r;
}
__device__ __forceinline__ uint32_t s2u(const void* p) {
    uint32_t a;
    asm("{ .reg .u64 t; cvta.to.shared.u64 t, %1; cvt.u32.u64 %0, t; }" : "=r"(a) : "l"(p));
    return a;
}
__device__ __forceinline__ void cp16(uint32_t dst, const void* src) {
    asm volatile("cp.async.cg.shared.global [%0], [%1], 16;" :: "r"(dst), "l"(src) : "memory");
}
#define CP_COMMIT() asm volatile("cp.async.commit_group;" ::: "memory")
#define CP_WAIT(n)  asm volatile("cp.async.wait_group %0;" :: "n"(n) : "memory")

__device__ __forceinline__ void ldm_x4(uint32_t* r, uint32_t addr) {
    asm volatile("ldmatrix.sync.aligned.m8n8.x4.shared.b16 {%0,%1,%2,%3}, [%4];"
        : "=r"(r[0]), "=r"(r[1]), "=r"(r[2]), "=r"(r[3]) : "r"(addr));
}
__device__ __forceinline__ void ldm_x4t(uint32_t* r, uint32_t addr) {
    asm volatile("ldmatrix.sync.aligned.m8n8.x4.trans.shared.b16 {%0,%1,%2,%3}, [%4];"
        : "=r"(r[0]), "=r"(r[1]), "=r"(r[2]), "=r"(r[3]) : "r"(addr));
}
__device__ __forceinline__ void mma_f16(float* d, const uint32_t* a, uint32_t b0, uint32_t b1) {
    asm volatile(
        "mma.sync.aligned.m16n8k16.row.col.f32.f16.f16.f32 "
        "{%0,%1,%2,%3}, {%4,%5,%6,%7}, {%8,%9}, {%0,%1,%2,%3};"
        : "+f"(d[0]), "+f"(d[1]), "+f"(d[2]), "+f"(d[3])
        : "r"(a[0]), "r"(a[1]), "r"(a[2]), "r"(a[3]), "r"(b0), "r"(b1));
}

// ---------------------------------------------------------------------------
// Prep: blocks 0..255: 288 contiguous half2 of g_Wh each (coalesced, exact);
//       blocks 256..287: beta partials (4 input dims each). No stragglers.
// ---------------------------------------------------------------------------
__global__ void kan_prep(const float* __restrict__ W, const float* __restrict__ C,
                         const float* __restrict__ bias) {
    const int tid = threadIdx.x;
    if (blockIdx.x >= CONV_BLKS) {
        const int b = blockIdx.x - CONV_BLKS;   // 0..31
        if (tid < DOUT) {
            float s = 0.0f;
            #pragma unroll
            for (int q = 0; q < 4; ++q) {
                int i = b * 4 + q;
                s += bias[i * DOUT + tid] * C[i * DOUT + tid];
            }
            g_betap[b * DOUT + tid] = s;
        }
        return;
    }
    const int bid = blockIdx.x;                 // 0..255
    #pragma unroll
    for (int jj = 0; jj < 2; ++jj) {
        int t = tid + jj * 256;
        if (t < 288) {
            int j = bid * 288 + t;           // half2 index into g_Wh (< 73728)
            int o = j / (KTOT / 2);
            int r = j - o * (KTOT / 2);
            int k0 = 2 * r;
            int i1 = k0 / NB,       kb1 = k0 - i1 * NB;
            int i2 = (k0 + 1) / NB, kb2 = (k0 + 1) - i2 * NB;
            float v0 = W[((size_t)i1 * DOUT + o) * NB + kb1] * C[i1 * DOUT + o];
            float v1 = W[((size_t)i2 * DOUT + o) * NB + kb2] * C[i2 * DOUT + o];
            ((__half2*)g_Wh)[j] = __floats2half2_rn(v0, v1);
        }
    }
}

// ---------------------------------------------------------------------------
// One basis evaluation -> 9 fp16 k-rows of the A buffer (CF contiguous stores)
// ---------------------------------------------------------------------------
__device__ __forceinline__ void eval_feat(__half* Ast, int row, int ii, float xv) {
    float ax = fabsf(xv);
    float x2 = xv * xv;
    __half* d = Ast + (ii * NB) * ASTR + row;
    d[0 * ASTR] = __float2half_rn(xv);
    d[1 * ASTR] = __float2half_rn(x2);
    d[2 * ASTR] = __float2half_rn(x2 * xv);
    d[3 * ASTR] = __float2half_rn(__expf(xv));
    d[4 * ASTR] = __float2half_rn(__logf(ax + 1.0f));
    d[5 * ASTR] = __float2half_rn(sqrt_ap(ax));
    d[6 * ASTR] = __float2half_rn(tanh_ap(xv));
    d[7 * ASTR] = __float2half_rn(__sinf(xv));
    d[8 * ASTR] = __float2half_rn(ax);
}

// ---------------------------------------------------------------------------
// Main: fp16 ldmatrix mma, K=1152 (no padding), progressive cp.async B,
// split-K=4, fused last-block reduction. Grid (64, 4), 256 thr, 2 CTAs/SM.
// ---------------------------------------------------------------------------
__global__ __launch_bounds__(256, 2)
void kan_main(const float* __restrict__ x, float* __restrict__ out)
{
    extern __shared__ char smem[];
    __half* Bs = (__half*)(smem + OFF_BS);     // [128 n][296], cols 0..287 data
    __half* As = (__half*)(smem + OFF_AS);     // [144 k][72 m]
    __shared__ int s_last;

    const int tid   = threadIdx.x;
    const int lane  = tid & 31;
    const int warp  = tid >> 5;
    const int wm    = warp & 1;
    const int wn    = warp >> 1;
    const int g     = lane >> 2;
    const int tg    = lane & 3;
    const int t4    = lane >> 3;
    const int r8    = lane & 7;
    const int tile  = blockIdx.x;
    const int split = blockIdx.y;
    const int bm0   = tile * BM;
    const int i0    = split * ISL;

    const int frow  = tid & 63;
    const int fbase = (tid >> 6) * 4;    // 4 dims per thread per chunk
    const float* xrow = x + (size_t)(bm0 + frow) * DIN + i0;

    // --- cp.async B slice [128 n][288 k] in 2 progressive groups
    {
        const uint32_t bsb = s2u(Bs);
        const __half*  src0 = g_Wh + (size_t)split * KSLICE;
        #pragma unroll
        for (int c = 0; c < NCH; ++c) {
            #pragma unroll
            for (int jj = 0; jj < 9; ++jj) {
                int j = tid + jj * 256;          // 2304 x 16B per group
                int n = j / 18, q = j - n * 18;
                cp16(bsb + (uint32_t)(n * (BSTR * 2) + c * (KCH * 2) + q * 16),
                     src0 + (size_t)n * KTOT + c * KCH + q * 8);
            }
            CP_COMMIT();
        }
    }

    // --- prefetch x for both chunks
    float xc[4], xn[4];
    #pragma unroll
    for (int q = 0; q < 4; ++q) {
        xc[q] = xrow[fbase + q];
        xn[q] = xrow[FCH + fbase + q];
    }

    // --- ldmatrix lane base addresses
    uint32_t aAddr[2], bAddr[2];
    {
        const uint32_t asb = s2u(As), bsb = s2u(Bs);
        #pragma unroll
        for (int mt = 0; mt < 2; ++mt) {
            int m0 = wm * 32 + mt * 16;
            aAddr[mt] = asb + (uint32_t)(((t4 >> 1) * 8 + r8) * ASTR + m0 + (t4 & 1) * 8) * 2;
        }
        #pragma unroll
        for (int p = 0; p < 2; ++p) {
            int n = wn * 32 + p * 16 + (t4 >> 1) * 8 + r8;
            bAddr[p] = bsb + (uint32_t)(n * BSTR + (t4 & 1) * 8) * 2;
        }
    }

    float acc[2][4][4];
    #pragma unroll
    for (int mt = 0; mt < 2; ++mt)
        #pragma unroll
        for (int nt = 0; nt < 4; ++nt)
            #pragma unroll
            for (int e = 0; e < 4; ++e) acc[mt][nt][e] = 0.0f;

    // --- chunk 0 feats; wait for B group 0
    #pragma unroll
    for (int q = 0; q < 4; ++q) eval_feat(As, frow, fbase + q, xc[q]);
    CP_WAIT(1);
    __syncthreads();

    #pragma unroll
    for (int c = 0; c < NCH; ++c) {
        // --- 9 k16-steps on the A buffer
        #pragma unroll
        for (int s9 = 0; s9 < 9; ++s9) {
            const uint32_t kaOff = (uint32_t)(s9 * 16 * ASTR) * 2;
            const uint32_t kbOff = (uint32_t)((c * KCH + s9 * 16)) * 2;
            uint32_t a[2][4], bq[2][4];
            ldm_x4t(a[0], aAddr[0] + kaOff);
            ldm_x4t(a[1], aAddr[1] + kaOff);
            ldm_x4(bq[0], bAddr[0] + kbOff);
            ldm_x4(bq[1], bAddr[1] + kbOff);
            #pragma unroll
            for (int mt = 0; mt < 2; ++mt)
                #pragma unroll
                for (int nt = 0; nt < 4; ++nt)
                    mma_f16(acc[mt][nt], a[mt],
                            bq[nt >> 1][(nt & 1) * 2], bq[nt >> 1][(nt & 1) * 2 + 1]);
        }
        if (c == 0) {
            __syncthreads();     // A reads done
            #pragma unroll
            for (int q = 0; q < 4; ++q) eval_feat(As, frow, fbase + q, xn[q]);
            CP_WAIT(0);
            __syncthreads();     // chunk-1 feats + B group 1 visible
        }
    }

    // --- epilogue: write raw partials
    {
        float* base = g_part + (size_t)split * BATCH * DOUT;
        #pragma unroll
        for (int nt = 0; nt < 4; ++nt) {
            int col = wn * 32 + nt * 8 + tg * 2;
            #pragma unroll
            for (int mt = 0; mt < 2; ++mt) {
                int row = bm0 + wm * 32 + mt * 16 + g;
                float* p = base + (size_t)row * DOUT + col;
                *(float2*)p              = make_float2(acc[mt][nt][0], acc[mt][nt][1]);
                *(float2*)(p + 8 * DOUT) = make_float2(acc[mt][nt][2], acc[mt][nt][3]);
            }
        }
    }

    // --- last split block of this tile reduces 4 partial planes + beta -> out
    __threadfence();
    __syncthreads();
    if (tid == 0)
        s_last = (atomicAdd(&g_cnt[tile], 1) == KSPLIT - 1);
    __syncthreads();

    if (s_last) {
        __threadfence();
        float* sb = (float*)smem;     // Bs area is free now
        if (tid < DOUT) {
            float s = 0.0f;
            #pragma unroll
            for (int b = 0; b < BETA_BLKS; ++b) s += __ldcg(g_betap + b * DOUT + tid);
            sb[tid] = s;
        }
        __syncthreads();

        const float4* pp = (const float4*)g_part;
        const size_t plane = (size_t)BATCH * DOUT / 4;
        const size_t base4 = (size_t)bm0 * (DOUT / 4);
        #pragma unroll
        for (int idx = tid; idx < BM * DOUT / 4; idx += 256) {
            size_t o = base4 + idx;
            float4 p0 = __ldcg(pp + o);
            float4 p1 = __ldcg(pp + plane + o);
            float4 p2 = __ldcg(pp + 2 * plane + o);
            float4 p3 = __ldcg(pp + 3 * plane + o);
            float4 be = ((const float4*)sb)[idx & 31];
            float4 s;
            s.x = (p0.x + p1.x) + (p2.x + p3.x) + be.x;
            s.y = (p0.y + p1.y) + (p2.y + p3.y) + be.y;
            s.z = (p0.z + p1.z) + (p2.z + p3.z) + be.z;
            s.w = (p0.w + p1.w) + (p2.w + p3.w) + be.w;
            ((float4*)out)[o] = s;
        }
        __syncthreads();
        if (tid == 0) g_cnt[tile] = 0;
    }
}

// ---------------------------------------------------------------------------
extern "C" void kernel_launch(void* const* d_in, const int* in_sizes, int n_in,
                              void* d_out, int out_size) {
    const float* x    = (const float*)d_in[0];   // [4096,128]
    const float* W    = (const float*)d_in[1];   // [128,128,9]
    const float* bias = (const float*)d_in[2];   // [128,128]
    const float* C    = (const float*)d_in[3];   // [128,128]
    float* out        = (float*)d_out;           // [4096,128]
    (void)in_sizes; (void)n_in; (void)out_size;

    cudaFuncSetAttribute(kan_main, cudaFuncAttributeMaxDynamicSharedMemorySize, SMEM_BYTES);

    kan_prep<<<PREP_BLKS, 256>>>(W, C, bias);
    kan_main<<<dim3(NTILE, KSPLIT), 256, SMEM_BYTES>>>(x, out);
}